// round 4
// baseline (speedup 1.0000x reference)
#include <cuda_runtime.h>
#include <cuda_bf16.h>
#include <cstdint>

#define N_ROWS  16384
#define DDIM    512
#define K_CODES 8192
#define KQ      128           // int32 (4xint8) k-steps per row

#define MT 128                // rows per CTA
#define NT 128                // codes per N tile
#define NTILES 64             // K_CODES / NT
#define CAP 32
#define MARGIN 1.2e-3f

// ---- scratch (__device__ globals: no cudaMalloc allowed) --------------------
__device__ float  g_snorm[N_ROWS];
__device__ float  g_cnorm[K_CODES];
__device__ float  g_sx[N_ROWS];          // per-row x scale
__device__ float  g_sc[K_CODES];         // per-code scale
__device__ int    g_idx[N_ROWS];
__device__ double g_loss;
__device__ int    g_xq[(size_t)N_ROWS * KQ];       // packed int8 x, row-major
__device__ int    g_cqT[(size_t)KQ * K_CODES];     // packed int8 codebook, TRANSPOSED [kq][code]
__device__ int    g_ccount[N_ROWS];
__device__ int    g_cand[(size_t)N_ROWS * CAP];

// ---- dynamic smem layout ------------------------------------------------------
#define AS_OFF 0               // 128 rows x 512B          = 65536
#define BS_OFF 65536           // 2 bufs x (128kq x 512B)  = 131072
#define CN_OFF 196608          // 2 x 512
#define SC_OFF 197632          // 2 x 512
#define SX_OFF 198656          // 512
#define SMEM_SZ 199680

static __device__ __forceinline__ uint32_t smem_u32(const void* p) {
    uint32_t a;
    asm("{ .reg .u64 t; cvta.to.shared.u64 t, %1; cvt.u32.u64 %0, t; }"
        : "=r"(a) : "l"(p));
    return a;
}
static __device__ __forceinline__ void cp16(uint32_t dst, const void* src) {
    asm volatile("cp.async.ca.shared.global [%0], [%1], 16;"
                 :: "r"(dst), "l"(src) : "memory");
}
static __device__ __forceinline__ void cp_commit() {
    asm volatile("cp.async.commit_group;" ::: "memory");
}
static __device__ __forceinline__ void cp_wait_all() {
    asm volatile("cp.async.wait_group 0;" ::: "memory");
}

// ---------------------------------------------------------------------------
// Kernel 1: int8 quantize (per-row scale) + exact fp32 row norms.
// One warp per row. x rows -> g_xq (row-major). codebook rows -> g_cqT
// (transposed). Also zeroes loss + candidate counts (graph-replay safe).
// ---------------------------------------------------------------------------
__global__ void quant_kernel(const float* __restrict__ x,
                             const float* __restrict__ cb) {
    int gtid = blockIdx.x * blockDim.x + threadIdx.x;
    if (gtid == 0) g_loss = 0.0;
    if (gtid < N_ROWS) g_ccount[gtid] = 0;
    int warp = gtid >> 5;
    int lane = threadIdx.x & 31;
    if (warp >= N_ROWS + K_CODES) return;
    bool isx = warp < N_ROWS;
    int row = isx ? warp : warp - N_ROWS;
    const float4* base = (const float4*)((isx ? x : cb) + (size_t)row * DDIM);

    float4 v[4];
    float s = 0.f, amax = 0.f;
#pragma unroll
    for (int j = 0; j < 4; j++) {
        v[j] = base[lane + 32 * j];
        s += v[j].x * v[j].x + v[j].y * v[j].y + v[j].z * v[j].z + v[j].w * v[j].w;
        amax = fmaxf(amax, fmaxf(fmaxf(fabsf(v[j].x), fabsf(v[j].y)),
                                 fmaxf(fabsf(v[j].z), fabsf(v[j].w))));
    }
#pragma unroll
    for (int o = 16; o; o >>= 1) {
        s    += __shfl_xor_sync(0xffffffff, s, o);
        amax  = fmaxf(amax, __shfl_xor_sync(0xffffffff, amax, o));
    }
    float scale = (amax > 0.f) ? amax / 127.f : 1.f;
    float inv   = (amax > 0.f) ? 127.f / amax : 0.f;
#pragma unroll
    for (int j = 0; j < 4; j++) {
        int q0 = __float2int_rn(v[j].x * inv);
        int q1 = __float2int_rn(v[j].y * inv);
        int q2 = __float2int_rn(v[j].z * inv);
        int q3 = __float2int_rn(v[j].w * inv);
        int packed = (q0 & 0xff) | ((q1 & 0xff) << 8) |
                     ((q2 & 0xff) << 16) | ((q3 & 0xff) << 24);
        int kq = lane + 32 * j;
        if (isx) g_xq[(size_t)row * KQ + kq] = packed;
        else     g_cqT[(size_t)kq * K_CODES + row] = packed;
    }
    if (lane == 0) {
        if (isx) { g_snorm[row] = s; g_sx[row] = scale; }
        else     { g_cnorm[row] = s; g_sc[row] = scale; }
    }
}

// ---------------------------------------------------------------------------
// Kernel 2: dp4a int8 GEMM filter. CTA = 128 rows (A resident), streams 64
// N-tiles of 128 codes (double-buffered cp.async). 8x8 register tile/thread.
// v = cn - 2*sx*sc*dot; register running row-min via shfl; candidate collect.
// ---------------------------------------------------------------------------
__global__ void __launch_bounds__(256, 1)
vq_gemm_kernel() {
    extern __shared__ char smem[];
    const uint32_t sb = smem_u32(smem);
    const int tid = threadIdx.x;
    const int tx  = tid & 15;       // code group
    const int ty  = tid >> 4;       // row group (8 rows: ty*8..ty*8+7)
    const int row0 = blockIdx.x * MT;

    // prologue: A tile + sx + B tile 0 + cn/sc tile 0, one cp.async group
    for (int s2 = tid; s2 < 4096; s2 += 256) {
        int r = s2 >> 5, o = s2 & 31;
        cp16(sb + AS_OFF + r * 512 + o * 16,
             g_xq + (size_t)(row0 + r) * KQ + o * 4);
    }
    if (tid < 32) cp16(sb + SX_OFF + tid * 16, g_sx + row0 + tid * 4);
    // B tile 0
    for (int s2 = tid; s2 < 4096; s2 += 256) {
        int kq = s2 >> 5, o = s2 & 31;
        cp16(sb + BS_OFF + kq * 512 + o * 16,
             g_cqT + (size_t)kq * K_CODES + o * 4);
    }
    if (tid < 32)
        cp16(sb + CN_OFF + tid * 16, g_cnorm + tid * 4);
    else if (tid < 64)
        cp16(sb + SC_OFF + (tid - 32) * 16, g_sc + (tid - 32) * 4);
    cp_commit();

    float runmin[8];
#pragma unroll
    for (int i = 0; i < 8; i++) runmin[i] = 3.4e38f;

    const int* Asp = (const int*)(smem + AS_OFF);

    for (int t = 0; t < NTILES; t++) {
        const int buf = t & 1;
        cp_wait_all();
        __syncthreads();
        if (t + 1 < NTILES) {
            const int nb = buf ^ 1;
            for (int s2 = tid; s2 < 4096; s2 += 256) {
                int kq = s2 >> 5, o = s2 & 31;
                cp16(sb + BS_OFF + nb * 65536 + kq * 512 + o * 16,
                     g_cqT + (size_t)kq * K_CODES + (t + 1) * NT + o * 4);
            }
            if (tid < 32)
                cp16(sb + CN_OFF + nb * 512 + tid * 16,
                     g_cnorm + (t + 1) * NT + tid * 4);
            else if (tid < 64)
                cp16(sb + SC_OFF + nb * 512 + (tid - 32) * 16,
                     g_sc + (t + 1) * NT + (tid - 32) * 4);
            cp_commit();
        }

        const int* Bsp = (const int*)(smem + BS_OFF + buf * 65536);
        int acc[8][8];
#pragma unroll
        for (int i = 0; i < 8; i++)
#pragma unroll
            for (int j = 0; j < 8; j++) acc[i][j] = 0;

#pragma unroll 1
        for (int kq4 = 0; kq4 < 32; kq4++) {
            int4 av[8];
#pragma unroll
            for (int i = 0; i < 8; i++)
                av[i] = *(const int4*)&Asp[(ty * 8 + i) * KQ + kq4 * 4];
#pragma unroll
            for (int kk = 0; kk < 4; kk++) {
                int4 b0 = *(const int4*)&Bsp[(kq4 * 4 + kk) * NT + tx * 4];
                int4 b1 = *(const int4*)&Bsp[(kq4 * 4 + kk) * NT + tx * 4 + 64];
                int br[8] = {b0.x, b0.y, b0.z, b0.w, b1.x, b1.y, b1.z, b1.w};
#pragma unroll
                for (int i = 0; i < 8; i++) {
                    int a = (kk == 0) ? av[i].x : (kk == 1) ? av[i].y
                          : (kk == 2) ? av[i].z : av[i].w;
#pragma unroll
                    for (int j = 0; j < 8; j++)
                        acc[i][j] = __dp4a(a, br[j], acc[i][j]);
                }
            }
        }

        // epilogue (register-local; no barriers)
        const float* cn = (const float*)(smem + CN_OFF + buf * 512);
        const float* sc = (const float*)(smem + SC_OFF + buf * 512);
        const float* sxs = (const float*)(smem + SX_OFF);
        float scj[8], cnj[8];
#pragma unroll
        for (int j = 0; j < 8; j++) {
            int c = tx * 4 + (j >> 2) * 64 + (j & 3);
            scj[j] = sc[c];
            cnj[j] = cn[c];
        }
#pragma unroll
        for (int i = 0; i < 8; i++) {
            int lrow = ty * 8 + i;
            float fs = -2.f * sxs[lrow];
            float v[8], vmin = 3.4e38f;
#pragma unroll
            for (int j = 0; j < 8; j++) {
                v[j] = fmaf(fs * scj[j], (float)acc[i][j], cnj[j]);
                vmin = fminf(vmin, v[j]);
            }
#pragma unroll
            for (int o = 8; o; o >>= 1)
                vmin = fminf(vmin, __shfl_xor_sync(0xffffffff, vmin, o));
            runmin[i] = fminf(runmin[i], vmin);
            float thr = runmin[i] + MARGIN;
            int grow = row0 + lrow;
#pragma unroll
            for (int j = 0; j < 8; j++) {
                if (v[j] <= thr) {
                    int pos = atomicAdd(&g_ccount[grow], 1);
                    if (pos < CAP)
                        g_cand[(size_t)grow * CAP + pos] =
                            t * NT + tx * 4 + (j >> 2) * 64 + (j & 3);
                }
            }
        }
    }
}

// ---------------------------------------------------------------------------
// Kernel 3: exact fp32 rescoring (reference rounding, lowest-index ties).
// One warp per row.
// ---------------------------------------------------------------------------
__global__ void __launch_bounds__(256)
exact_kernel(const float* __restrict__ x, const float* __restrict__ cb) {
    int row = (blockIdx.x * blockDim.x + threadIdx.x) >> 5;
    int lane = threadIdx.x & 31;
    if (row >= N_ROWS) return;
    float xr[16];
    const float* xp = x + (size_t)row * DDIM;
#pragma unroll
    for (int e = 0; e < 16; e++) xr[e] = xp[lane + e * 32];
    const float s = g_snorm[row];
    const int cnt = g_ccount[row];
    float bd = 3.4e38f;
    int   bi = K_CODES;

    if (cnt <= CAP) {
        for (int i = 0; i < cnt; i++) {
            int k = g_cand[(size_t)row * CAP + i];
            const float* cp = cb + (size_t)k * DDIM;
            float t = 0.f;
#pragma unroll
            for (int e = 0; e < 16; e++) t = fmaf(xr[e], cp[lane + e * 32], t);
#pragma unroll
            for (int o = 16; o; o >>= 1) t += __shfl_xor_sync(0xffffffff, t, o);
            float dist = (s - 2.0f * t) + g_cnorm[k];
            if (dist < bd || (dist == bd && k < bi)) { bd = dist; bi = k; }
        }
    } else {  // overflow fallback: exact scan
        for (int k = 0; k < K_CODES; k++) {
            const float* cp = cb + (size_t)k * DDIM;
            float t = 0.f;
#pragma unroll
            for (int e = 0; e < 16; e++) t = fmaf(xr[e], cp[lane + e * 32], t);
#pragma unroll
            for (int o = 16; o; o >>= 1) t += __shfl_xor_sync(0xffffffff, t, o);
            float dist = (s - 2.0f * t) + g_cnorm[k];
            if (dist < bd) { bd = dist; bi = k; }
        }
    }
    if (lane == 0) g_idx[row] = bi;
}

// ---------------------------------------------------------------------------
// Kernel 4: gather z_q, straight-through output, fp64 loss accumulation.
// ---------------------------------------------------------------------------
__global__ void gather_loss_kernel(const float* __restrict__ x,
                                   const float* __restrict__ cb,
                                   float* __restrict__ out) {
    __shared__ double part[256];
    double lsum = 0.0;
    const size_t total = (size_t)N_ROWS * DDIM;
    for (size_t e = (size_t)blockIdx.x * blockDim.x + threadIdx.x;
         e < total; e += (size_t)gridDim.x * blockDim.x) {
        int n = (int)(e >> 9);
        int d = (int)(e & 511);
        int k = g_idx[n];
        float zq = cb[(size_t)k * DDIM + d];
        float ze = x[e];
        float diff = zq - ze;
        out[e] = ze + diff;
        lsum += (double)diff * (double)diff;
    }
    part[threadIdx.x] = lsum;
    __syncthreads();
    for (int s = 128; s; s >>= 1) {
        if (threadIdx.x < s) part[threadIdx.x] += part[threadIdx.x + s];
        __syncthreads();
    }
    if (threadIdx.x == 0) atomicAdd(&g_loss, part[0]);
}

// ---------------------------------------------------------------------------
// Kernel 5: losses + indices.
// ---------------------------------------------------------------------------
__global__ void finalize_kernel(float* __restrict__ out, long long out_size) {
    const long long base = (long long)N_ROWS * DDIM;
    if (blockIdx.x == 0 && threadIdx.x == 0 && out_size >= base + 2) {
        float loss = (float)(g_loss / ((double)N_ROWS * (double)DDIM));
        out[base]     = loss;
        out[base + 1] = loss;
    }
    if (out_size >= base + 2 + N_ROWS) {
        for (int n = blockIdx.x * blockDim.x + threadIdx.x; n < N_ROWS;
             n += gridDim.x * blockDim.x)
            out[base + 2 + n] = (float)g_idx[n];
    }
}

// ---------------------------------------------------------------------------
extern "C" void kernel_launch(void* const* d_in, const int* in_sizes, int n_in,
                              void* d_out, int out_size) {
    const float* x  = (const float*)d_in[0];
    const float* cb = (const float*)d_in[1];
    float* out = (float*)d_out;

    cudaFuncSetAttribute(vq_gemm_kernel,
                         cudaFuncAttributeMaxDynamicSharedMemorySize, SMEM_SZ);

    quant_kernel<<<(N_ROWS + K_CODES) / 8, 256>>>(x, cb);
    vq_gemm_kernel<<<N_ROWS / MT, 256, SMEM_SZ>>>();
    exact_kernel<<<N_ROWS / 8, 256>>>(x, cb);
    gather_loss_kernel<<<2048, 256>>>(x, cb, out);
    finalize_kernel<<<64, 256>>>(out, (long long)out_size);
}

// round 5
// speedup vs baseline: 2.5097x; 2.5097x over previous
#include <cuda_runtime.h>
#include <cuda_fp16.h>
#include <cstdint>

#define N_ROWS  16384
#define DDIM    512
#define K_CODES 8192

#define MT 128                 // rows per CTA
#define NTT 128                // codes per tile
#define NTILES 64              // K_CODES / NTT
#define KCH 128                // k per chunk
#define CAP 32
#define MARGIN 6.0e-4f

// ---- scratch (__device__ globals; no cudaMalloc allowed) --------------------
__device__ float  g_snorm[N_ROWS];
__device__ float  g_cnorm[K_CODES];
__device__ int    g_idx[N_ROWS];
__device__ double g_loss;
__device__ __half g_xh[(size_t)N_ROWS * DDIM];
__device__ __half g_ch[(size_t)K_CODES * DDIM];
__device__ int    g_ccount[N_ROWS];
__device__ int    g_cand[(size_t)N_ROWS * CAP];

// ---- dynamic smem ------------------------------------------------------------
#define AS_OFF 0               // 64 k8-blocks x 128 rows x 16B = 131072
#define BS_OFF 131072          // 2 bufs x (16 k8 x 128 codes x 16B) = 65536
#define SMEM_SZ 196608

static __device__ __forceinline__ uint32_t smem_u32(const void* p) {
    uint32_t a;
    asm("{ .reg .u64 t; cvta.to.shared.u64 t, %1; cvt.u32.u64 %0, t; }"
        : "=r"(a) : "l"(p));
    return a;
}
static __device__ __forceinline__ void cp16(uint32_t dst, const void* src) {
    asm volatile("cp.async.ca.shared.global [%0], [%1], 16;"
                 :: "r"(dst), "l"(src) : "memory");
}
static __device__ __forceinline__ void cp_commit() {
    asm volatile("cp.async.commit_group;" ::: "memory");
}
static __device__ __forceinline__ void cp_wait_all() {
    asm volatile("cp.async.wait_group 0;" ::: "memory");
}

// ---------------------------------------------------------------------------
// Kernel 1: fp16 convert + exact fp32 row norms; zero loss + counters.
// One warp per row.
// ---------------------------------------------------------------------------
__global__ void convert_kernel(const float* __restrict__ x,
                               const float* __restrict__ cb) {
    int gtid = blockIdx.x * blockDim.x + threadIdx.x;
    if (gtid == 0) g_loss = 0.0;
    if (gtid < N_ROWS) g_ccount[gtid] = 0;
    int warp = gtid >> 5;
    int lane = threadIdx.x & 31;
    if (warp >= N_ROWS + K_CODES) return;
    bool isx = warp < N_ROWS;
    int row = isx ? warp : warp - N_ROWS;
    const float4* base = (const float4*)((isx ? x : cb) + (size_t)row * DDIM);
    __half2* dst = (__half2*)((isx ? g_xh : g_ch) + (size_t)row * DDIM);

    float s = 0.f;
#pragma unroll
    for (int j = 0; j < 4; j++) {
        float4 v = base[lane + 32 * j];
        s += v.x * v.x + v.y * v.y + v.z * v.z + v.w * v.w;
        dst[(lane + 32 * j) * 2]     = __floats2half2_rn(v.x, v.y);
        dst[(lane + 32 * j) * 2 + 1] = __floats2half2_rn(v.z, v.w);
    }
#pragma unroll
    for (int o = 16; o; o >>= 1) s += __shfl_xor_sync(0xffffffff, s, o);
    if (lane == 0) {
        if (isx) g_snorm[row] = s;
        else     g_cnorm[row] = s;
    }
}

// ---------------------------------------------------------------------------
// Kernel 2: HFMA2 packed-fp16 filter GEMM. CTA = 128 rows (A resident),
// streams 64 code-tiles x 4 k-chunks (double-buffered cp.async).
// acc half2 holds even/odd-k partial dots; v = cn - 2*(lo+hi).
// Register running row-min + candidate collection (round-4-proven).
// ---------------------------------------------------------------------------
__global__ void __launch_bounds__(256, 1)
vq_gemm_kernel() {
    extern __shared__ char smem[];
    const uint32_t sb = smem_u32(smem);
    const int tid = threadIdx.x;
    const int tx  = tid & 15;          // code lane: codes tx + 16*j
    const int ty  = tid >> 4;          // row group: rows ty*8 + i
    const int row0 = blockIdx.x * MT;

    // prologue: resident A (64 k8-blocks x 128 rows) + B chunk 0, one group
    for (int c = tid; c < 8192; c += 256) {
        int r = c & 127, k8 = c >> 7;
        cp16(sb + AS_OFF + (k8 * 128 + r) * 16,
             g_xh + ((size_t)(row0 + r) * DDIM + k8 * 8));
    }
    for (int c = tid; c < 2048; c += 256) {
        int code = c & 127, k8l = c >> 7;
        cp16(sb + BS_OFF + (k8l * 128 + code) * 16,
             g_ch + ((size_t)code * DDIM + k8l * 8));
    }
    cp_commit();

    float runmin[8];
#pragma unroll
    for (int i = 0; i < 8; i++) runmin[i] = 3.4e38f;

    __half2 acc[8][8];

    for (int t = 0; t < NTILES; t++) {
        for (int kc = 0; kc < 4; kc++) {
            const int s = t * 4 + kc;
            const int buf = s & 1;
            cp_wait_all();
            __syncthreads();
            if (s + 1 < NTILES * 4) {     // prefetch next chunk
                const int nt = (s + 1) >> 2, nkc = (s + 1) & 3;
                const int nb = buf ^ 1;
                for (int c = tid; c < 2048; c += 256) {
                    int code = c & 127, k8l = c >> 7;
                    cp16(sb + BS_OFF + nb * 32768 + (k8l * 128 + code) * 16,
                         g_ch + ((size_t)(nt * NTT + code) * DDIM +
                                 (nkc * 16 + k8l) * 8));
                }
                cp_commit();
            }
            if (kc == 0) {
#pragma unroll
                for (int i = 0; i < 8; i++)
#pragma unroll
                    for (int j = 0; j < 8; j++)
                        acc[i][j] = __half2half2(__ushort_as_half(0));
            }

            const uint32_t abase = sb + AS_OFF + kc * 16 * 2048;
            const uint32_t bbase = sb + BS_OFF + buf * 32768;
#pragma unroll 2
            for (int k8 = 0; k8 < 16; k8++) {
                uint4 av[8], bv[8];
#pragma unroll
                for (int i = 0; i < 8; i++)
                    av[i] = *(const uint4*)(smem + (abase - sb) +
                                            (k8 * 128 + ty * 8 + i) * 16);
#pragma unroll
                for (int j = 0; j < 8; j++)
                    bv[j] = *(const uint4*)(smem + (bbase - sb) +
                                            (k8 * 128 + tx + 16 * j) * 16);
#pragma unroll
                for (int i = 0; i < 8; i++) {
                    const __half2* ah = (const __half2*)&av[i];
#pragma unroll
                    for (int j = 0; j < 8; j++) {
                        const __half2* bh = (const __half2*)&bv[j];
#pragma unroll
                        for (int p = 0; p < 4; p++)
                            acc[i][j] = __hfma2(ah[p], bh[p], acc[i][j]);
                    }
                }
            }
        }

        // ---- epilogue: v = cn - 2*(lo+hi); running row-min; collect ----
        float cnj[8];
#pragma unroll
        for (int j = 0; j < 8; j++) cnj[j] = g_cnorm[t * NTT + tx + 16 * j];
#pragma unroll
        for (int i = 0; i < 8; i++) {
            int grow = row0 + ty * 8 + i;
            float v[8], vmin = 3.4e38f;
#pragma unroll
            for (int j = 0; j < 8; j++) {
                float2 f = __half22float2(acc[i][j]);
                v[j] = fmaf(-2.f, f.x + f.y, cnj[j]);
                vmin = fminf(vmin, v[j]);
            }
#pragma unroll
            for (int o = 8; o; o >>= 1)
                vmin = fminf(vmin, __shfl_xor_sync(0xffffffff, vmin, o));
            runmin[i] = fminf(runmin[i], vmin);
            float thr = runmin[i] + MARGIN;
#pragma unroll
            for (int j = 0; j < 8; j++) {
                if (v[j] <= thr) {
                    int pos = atomicAdd(&g_ccount[grow], 1);
                    if (pos < CAP)
                        g_cand[(size_t)grow * CAP + pos] = t * NTT + tx + 16 * j;
                }
            }
        }
    }
}

// ---------------------------------------------------------------------------
// Kernel 3: exact fp32 rescoring (reference rounding, lowest-index ties).
// One warp per row; full-scan fallback on CAP overflow.
// ---------------------------------------------------------------------------
__global__ void __launch_bounds__(256)
exact_kernel(const float* __restrict__ x, const float* __restrict__ cb) {
    int row = (blockIdx.x * blockDim.x + threadIdx.x) >> 5;
    int lane = threadIdx.x & 31;
    if (row >= N_ROWS) return;
    float xr[16];
    const float* xp = x + (size_t)row * DDIM;
#pragma unroll
    for (int e = 0; e < 16; e++) xr[e] = xp[lane + e * 32];
    const float s = g_snorm[row];
    const int cnt = g_ccount[row];
    float bd = 3.4e38f;
    int   bi = K_CODES;

    if (cnt <= CAP) {
        for (int i = 0; i < cnt; i++) {
            int k = g_cand[(size_t)row * CAP + i];
            const float* cp = cb + (size_t)k * DDIM;
            float t = 0.f;
#pragma unroll
            for (int e = 0; e < 16; e++) t = fmaf(xr[e], cp[lane + e * 32], t);
#pragma unroll
            for (int o = 16; o; o >>= 1) t += __shfl_xor_sync(0xffffffff, t, o);
            float dist = (s - 2.0f * t) + g_cnorm[k];
            if (dist < bd || (dist == bd && k < bi)) { bd = dist; bi = k; }
        }
    } else {  // overflow fallback: exact full scan
        for (int k = 0; k < K_CODES; k++) {
            const float* cp = cb + (size_t)k * DDIM;
            float t = 0.f;
#pragma unroll
            for (int e = 0; e < 16; e++) t = fmaf(xr[e], cp[lane + e * 32], t);
#pragma unroll
            for (int o = 16; o; o >>= 1) t += __shfl_xor_sync(0xffffffff, t, o);
            float dist = (s - 2.0f * t) + g_cnorm[k];
            if (dist < bd) { bd = dist; bi = k; }
        }
    }
    if (lane == 0) g_idx[row] = bi;
}

// ---------------------------------------------------------------------------
// Kernel 4: gather z_q, straight-through output, fp64 loss accumulation.
// ---------------------------------------------------------------------------
__global__ void gather_loss_kernel(const float* __restrict__ x,
                                   const float* __restrict__ cb,
                                   float* __restrict__ out) {
    __shared__ double part[256];
    double lsum = 0.0;
    const size_t total = (size_t)N_ROWS * DDIM;
    for (size_t e = (size_t)blockIdx.x * blockDim.x + threadIdx.x;
         e < total; e += (size_t)gridDim.x * blockDim.x) {
        int n = (int)(e >> 9);
        int d = (int)(e & 511);
        int k = g_idx[n];
        float zq = cb[(size_t)k * DDIM + d];
        float ze = x[e];
        float diff = zq - ze;
        out[e] = ze + diff;
        lsum += (double)diff * (double)diff;
    }
    part[threadIdx.x] = lsum;
    __syncthreads();
    for (int s = 128; s; s >>= 1) {
        if (threadIdx.x < s) part[threadIdx.x] += part[threadIdx.x + s];
        __syncthreads();
    }
    if (threadIdx.x == 0) atomicAdd(&g_loss, part[0]);
}

// ---------------------------------------------------------------------------
// Kernel 5: losses + indices.
// ---------------------------------------------------------------------------
__global__ void finalize_kernel(float* __restrict__ out, long long out_size) {
    const long long base = (long long)N_ROWS * DDIM;
    if (blockIdx.x == 0 && threadIdx.x == 0 && out_size >= base + 2) {
        float loss = (float)(g_loss / ((double)N_ROWS * (double)DDIM));
        out[base]     = loss;
        out[base + 1] = loss;
    }
    if (out_size >= base + 2 + N_ROWS) {
        for (int n = blockIdx.x * blockDim.x + threadIdx.x; n < N_ROWS;
             n += gridDim.x * blockDim.x)
            out[base + 2 + n] = (float)g_idx[n];
    }
}

// ---------------------------------------------------------------------------
extern "C" void kernel_launch(void* const* d_in, const int* in_sizes, int n_in,
                              void* d_out, int out_size) {
    const float* x  = (const float*)d_in[0];
    const float* cb = (const float*)d_in[1];
    float* out = (float*)d_out;

    cudaFuncSetAttribute(vq_gemm_kernel,
                         cudaFuncAttributeMaxDynamicSharedMemorySize, SMEM_SZ);

    convert_kernel<<<(N_ROWS + K_CODES) / 8, 256>>>(x, cb);
    vq_gemm_kernel<<<N_ROWS / MT, 256, SMEM_SZ>>>();
    exact_kernel<<<N_ROWS / 8, 256>>>(x, cb);
    gather_loss_kernel<<<2048, 256>>>(x, cb, out);
    finalize_kernel<<<64, 256>>>(out, (long long)out_size);
}

// round 6
// speedup vs baseline: 2.8359x; 1.1300x over previous
#include <cuda_runtime.h>
#include <cuda_fp16.h>
#include <cstdint>

#define N_ROWS  16384
#define DDIM    512
#define K_CODES 8192

#define MT 112                 // rows per CTA (147 CTAs = one wave on 148 SMs)
#define NCTA 147
#define NTT 128                // codes per tile
#define NTILES 64              // K_CODES / NTT
#define CAP 32
#define MARGIN 6.0e-4f

// ---- scratch (__device__ globals; no cudaMalloc allowed) --------------------
__device__ float  g_snorm[N_ROWS];
__device__ float  g_cnorm[K_CODES];
__device__ int    g_idx[N_ROWS];
__device__ double g_loss;
__device__ __half g_xh[(size_t)N_ROWS * DDIM];
__device__ __half g_ch[(size_t)K_CODES * DDIM];
__device__ int    g_ccount[N_ROWS];
__device__ int    g_cand[(size_t)N_ROWS * CAP];

// ---- dynamic smem ------------------------------------------------------------
#define AS_OFF 0               // 64 k8-blocks x 112 rows x 16B = 114688
#define BS_OFF 114688          // 2 bufs x (16 k8 x 128 codes x 16B) = 65536
#define SMEM_SZ 180224

static __device__ __forceinline__ uint32_t smem_u32(const void* p) {
    uint32_t a;
    asm("{ .reg .u64 t; cvta.to.shared.u64 t, %1; cvt.u32.u64 %0, t; }"
        : "=r"(a) : "l"(p));
    return a;
}
static __device__ __forceinline__ void cp16(uint32_t dst, const void* src) {
    asm volatile("cp.async.ca.shared.global [%0], [%1], 16;"
                 :: "r"(dst), "l"(src) : "memory");
}
static __device__ __forceinline__ void cp_commit() {
    asm volatile("cp.async.commit_group;" ::: "memory");
}
static __device__ __forceinline__ void cp_wait_all() {
    asm volatile("cp.async.wait_group 0;" ::: "memory");
}

// ---------------------------------------------------------------------------
// Kernel 1: fp16 convert + exact fp32 row norms; zero loss + counters.
// One warp per row.
// ---------------------------------------------------------------------------
__global__ void convert_kernel(const float* __restrict__ x,
                               const float* __restrict__ cb) {
    int gtid = blockIdx.x * blockDim.x + threadIdx.x;
    if (gtid == 0) g_loss = 0.0;
    if (gtid < N_ROWS) g_ccount[gtid] = 0;
    int warp = gtid >> 5;
    int lane = threadIdx.x & 31;
    if (warp >= N_ROWS + K_CODES) return;
    bool isx = warp < N_ROWS;
    int row = isx ? warp : warp - N_ROWS;
    const float4* base = (const float4*)((isx ? x : cb) + (size_t)row * DDIM);
    __half2* dst = (__half2*)((isx ? g_xh : g_ch) + (size_t)row * DDIM);

    float s = 0.f;
#pragma unroll
    for (int j = 0; j < 4; j++) {
        float4 v = base[lane + 32 * j];
        s += v.x * v.x + v.y * v.y + v.z * v.z + v.w * v.w;
        dst[(lane + 32 * j) * 2]     = __floats2half2_rn(v.x, v.y);
        dst[(lane + 32 * j) * 2 + 1] = __floats2half2_rn(v.z, v.w);
    }
#pragma unroll
    for (int o = 16; o; o >>= 1) s += __shfl_xor_sync(0xffffffff, s, o);
    if (lane == 0) {
        if (isx) g_snorm[row] = s;
        else     g_cnorm[row] = s;
    }
}

// ---------------------------------------------------------------------------
// Kernel 2: HFMA2 packed-fp16 filter GEMM. 147 CTAs x 112 rows = one full
// wave on 148 SMs. A resident in smem; B streamed double-buffered.
// Thread tile 7 rows x 8 codes. Register running row-min + candidate collect.
// ---------------------------------------------------------------------------
__global__ void __launch_bounds__(256, 1)
vq_gemm_kernel() {
    extern __shared__ char smem[];
    const uint32_t sb = smem_u32(smem);
    const int tid = threadIdx.x;
    const int tx  = tid & 15;          // code lane: codes tx + 16*j
    const int ty  = tid >> 4;          // row group: rows ty*7 + i
    const int row0 = blockIdx.x * MT;

    // prologue: resident A (64 k8-blocks x 112 rows, clamped) + B chunk 0
    for (int c = tid; c < 64 * MT; c += 256) {
        int r = c % MT, k8 = c / MT;
        int gr = row0 + r; if (gr >= N_ROWS) gr = N_ROWS - 1;
        cp16(sb + AS_OFF + (k8 * MT + r) * 16,
             g_xh + ((size_t)gr * DDIM + k8 * 8));
    }
    for (int c = tid; c < 2048; c += 256) {
        int code = c & 127, k8l = c >> 7;
        cp16(sb + BS_OFF + (k8l * 128 + code) * 16,
             g_ch + ((size_t)code * DDIM + k8l * 8));
    }
    cp_commit();

    float runmin[7];
#pragma unroll
    for (int i = 0; i < 7; i++) runmin[i] = 3.4e38f;

    __half2 acc[7][8];

    for (int t = 0; t < NTILES; t++) {
        for (int kc = 0; kc < 4; kc++) {
            const int s = t * 4 + kc;
            const int buf = s & 1;
            cp_wait_all();
            __syncthreads();
            if (s + 1 < NTILES * 4) {     // prefetch next chunk
                const int nt = (s + 1) >> 2, nkc = (s + 1) & 3;
                const int nb = buf ^ 1;
                for (int c = tid; c < 2048; c += 256) {
                    int code = c & 127, k8l = c >> 7;
                    cp16(sb + BS_OFF + nb * 32768 + (k8l * 128 + code) * 16,
                         g_ch + ((size_t)(nt * NTT + code) * DDIM +
                                 (nkc * 16 + k8l) * 8));
                }
                cp_commit();
            }
            if (kc == 0) {
#pragma unroll
                for (int i = 0; i < 7; i++)
#pragma unroll
                    for (int j = 0; j < 8; j++)
                        acc[i][j] = __half2half2(__ushort_as_half(0));
            }

            const uint32_t aoff = AS_OFF + kc * 16 * (MT * 16);
            const uint32_t boff = BS_OFF + buf * 32768;
#pragma unroll 2
            for (int k8 = 0; k8 < 16; k8++) {
                uint4 av[7], bv[8];
#pragma unroll
                for (int i = 0; i < 7; i++)
                    av[i] = *(const uint4*)(smem + aoff +
                                            (k8 * MT + ty * 7 + i) * 16);
#pragma unroll
                for (int j = 0; j < 8; j++)
                    bv[j] = *(const uint4*)(smem + boff +
                                            (k8 * 128 + tx + 16 * j) * 16);
#pragma unroll
                for (int i = 0; i < 7; i++) {
                    const __half2* ah = (const __half2*)&av[i];
#pragma unroll
                    for (int j = 0; j < 8; j++) {
                        const __half2* bh = (const __half2*)&bv[j];
#pragma unroll
                        for (int p = 0; p < 4; p++)
                            acc[i][j] = __hfma2(ah[p], bh[p], acc[i][j]);
                    }
                }
            }
        }

        // ---- epilogue: v = cn - 2*(lo+hi); running row-min; collect ----
        float cnj[8];
#pragma unroll
        for (int j = 0; j < 8; j++) cnj[j] = g_cnorm[t * NTT + tx + 16 * j];
#pragma unroll
        for (int i = 0; i < 7; i++) {
            int grow = row0 + ty * 7 + i;
            float v[8], vmin = 3.4e38f;
#pragma unroll
            for (int j = 0; j < 8; j++) {
                float2 f = __half22float2(acc[i][j]);
                v[j] = fmaf(-2.f, f.x + f.y, cnj[j]);
                vmin = fminf(vmin, v[j]);
            }
#pragma unroll
            for (int o = 8; o; o >>= 1)
                vmin = fminf(vmin, __shfl_xor_sync(0xffffffff, vmin, o));
            runmin[i] = fminf(runmin[i], vmin);
            if (grow < N_ROWS) {
                float thr = runmin[i] + MARGIN;
#pragma unroll
                for (int j = 0; j < 8; j++) {
                    if (v[j] <= thr) {
                        int pos = atomicAdd(&g_ccount[grow], 1);
                        if (pos < CAP)
                            g_cand[(size_t)grow * CAP + pos] =
                                t * NTT + tx + 16 * j;
                    }
                }
            }
        }
    }
}

// ---------------------------------------------------------------------------
// Kernel 3: exact fp32 rescoring (reference rounding, lowest-index ties).
// One warp per row; full-scan fallback on CAP overflow.
// ---------------------------------------------------------------------------
__global__ void __launch_bounds__(256)
exact_kernel(const float* __restrict__ x, const float* __restrict__ cb) {
    int row = (blockIdx.x * blockDim.x + threadIdx.x) >> 5;
    int lane = threadIdx.x & 31;
    if (row >= N_ROWS) return;
    float xr[16];
    const float* xp = x + (size_t)row * DDIM;
#pragma unroll
    for (int e = 0; e < 16; e++) xr[e] = xp[lane + e * 32];
    const float s = g_snorm[row];
    const int cnt = g_ccount[row];
    float bd = 3.4e38f;
    int   bi = K_CODES;

    if (cnt <= CAP) {
        for (int i = 0; i < cnt; i++) {
            int k = g_cand[(size_t)row * CAP + i];
            const float* cp = cb + (size_t)k * DDIM;
            float t = 0.f;
#pragma unroll
            for (int e = 0; e < 16; e++) t = fmaf(xr[e], cp[lane + e * 32], t);
#pragma unroll
            for (int o = 16; o; o >>= 1) t += __shfl_xor_sync(0xffffffff, t, o);
            float dist = (s - 2.0f * t) + g_cnorm[k];
            if (dist < bd || (dist == bd && k < bi)) { bd = dist; bi = k; }
        }
    } else {  // overflow fallback: exact full scan
        for (int k = 0; k < K_CODES; k++) {
            const float* cp = cb + (size_t)k * DDIM;
            float t = 0.f;
#pragma unroll
            for (int e = 0; e < 16; e++) t = fmaf(xr[e], cp[lane + e * 32], t);
#pragma unroll
            for (int o = 16; o; o >>= 1) t += __shfl_xor_sync(0xffffffff, t, o);
            float dist = (s - 2.0f * t) + g_cnorm[k];
            if (dist < bd) { bd = dist; bi = k; }
        }
    }
    if (lane == 0) g_idx[row] = bi;
}

// ---------------------------------------------------------------------------
// Kernel 4: gather z_q, straight-through output, fp64 loss accumulation.
// ---------------------------------------------------------------------------
__global__ void gather_loss_kernel(const float* __restrict__ x,
                                   const float* __restrict__ cb,
                                   float* __restrict__ out) {
    __shared__ double part[256];
    double lsum = 0.0;
    const size_t total = (size_t)N_ROWS * DDIM;
    for (size_t e = (size_t)blockIdx.x * blockDim.x + threadIdx.x;
         e < total; e += (size_t)gridDim.x * blockDim.x) {
        int n = (int)(e >> 9);
        int d = (int)(e & 511);
        int k = g_idx[n];
        float zq = cb[(size_t)k * DDIM + d];
        float ze = x[e];
        float diff = zq - ze;
        out[e] = ze + diff;
        lsum += (double)diff * (double)diff;
    }
    part[threadIdx.x] = lsum;
    __syncthreads();
    for (int s = 128; s; s >>= 1) {
        if (threadIdx.x < s) part[threadIdx.x] += part[threadIdx.x + s];
        __syncthreads();
    }
    if (threadIdx.x == 0) atomicAdd(&g_loss, part[0]);
}

// ---------------------------------------------------------------------------
// Kernel 5: losses + indices.
// ---------------------------------------------------------------------------
__global__ void finalize_kernel(float* __restrict__ out, long long out_size) {
    const long long base = (long long)N_ROWS * DDIM;
    if (blockIdx.x == 0 && threadIdx.x == 0 && out_size >= base + 2) {
        float loss = (float)(g_loss / ((double)N_ROWS * (double)DDIM));
        out[base]     = loss;
        out[base + 1] = loss;
    }
    if (out_size >= base + 2 + N_ROWS) {
        for (int n = blockIdx.x * blockDim.x + threadIdx.x; n < N_ROWS;
             n += gridDim.x * blockDim.x)
            out[base + 2 + n] = (float)g_idx[n];
    }
}

// ---------------------------------------------------------------------------
extern "C" void kernel_launch(void* const* d_in, const int* in_sizes, int n_in,
                              void* d_out, int out_size) {
    const float* x  = (const float*)d_in[0];
    const float* cb = (const float*)d_in[1];
    float* out = (float*)d_out;

    cudaFuncSetAttribute(vq_gemm_kernel,
                         cudaFuncAttributeMaxDynamicSharedMemorySize, SMEM_SZ);

    convert_kernel<<<(N_ROWS + K_CODES) / 8, 256>>>(x, cb);
    vq_gemm_kernel<<<NCTA, 256, SMEM_SZ>>>();
    exact_kernel<<<N_ROWS / 8, 256>>>(x, cb);
    gather_loss_kernel<<<2048, 256>>>(x, cb, out);
    finalize_kernel<<<64, 256>>>(out, (long long)out_size);
}